// round 8
// baseline (speedup 1.0000x reference)
#include <cuda_runtime.h>
#include <cstdint>

// Problem constants
#define BB   2
#define SS   2048
#define HIDD 4096
#define NH   32
#define NKV  8
#define HD   128

// GEMM tiling
#define BM 128
#define BN 128
#define BKK 32
#define LDK 36
#define STAGE_FLOATS ((BM + BN) * LDK)

// Attention tiling / smem layout (floats)
#define ATT_LDQ 132
#define ATT_LDK 132
#define ATT_LDV 136
#define ATT_LDP 36
#define KH_OFF (128 * ATT_LDQ)
#define KCHUNK (32 * ATT_LDK)
#define VH_OFF (KH_OFF + 4 * KCHUNK)
#define VCHUNK (32 * ATT_LDV)
#define PS_OFF (VH_OFF + 4 * VCHUNK)
#define ATT_SMEM ((PS_OFF + 8 * 16 * ATT_LDP) * 4)  // 223232 bytes

// ---------------- scratch (static device globals; no runtime alloc) --------
__device__ float g_qproj[(size_t)BB * SS * HIDD];
__device__ float g_kvproj[(size_t)BB * SS * 2 * NKV * HD];
__device__ float g_q[(size_t)BB * NH * SS * HD];
__device__ float g_khi[(size_t)BB * NKV * SS * HD];
__device__ float g_klo[(size_t)BB * NKV * SS * HD];
__device__ float g_vhi[(size_t)BB * NKV * SS * HD];
__device__ float g_vlo[(size_t)BB * NKV * SS * HD];
__device__ float g_attn[(size_t)BB * SS * HIDD];
// tf32-pre-rounded GEMM operands
__device__ float g_hidr[(size_t)BB * SS * HIDD];
__device__ float g_wqr[(size_t)HIDD * HIDD];
__device__ float g_wkvr[(size_t)2 * NKV * HD * HIDD];
__device__ float g_wdr[(size_t)HIDD * HIDD];

// ---------------------------------------------------------------------------
// helpers
// ---------------------------------------------------------------------------
__device__ __forceinline__ uint32_t cvta_smem(const void* p) {
  return (uint32_t)__cvta_generic_to_shared(p);
}

__device__ __forceinline__ void cp_async16(uint32_t saddr, const void* gptr) {
  asm volatile("cp.async.cg.shared.global [%0], [%1], 16;\n" ::"r"(saddr), "l"(gptr));
}

__device__ __forceinline__ uint32_t f2tf32(float x) {
  uint32_t u;
  asm("cvt.rna.tf32.f32 %0, %1;\n" : "=r"(u) : "f"(x));
  return u;
}

__device__ __forceinline__ void mma_tf32(float* c, const uint32_t* a, const uint32_t* b) {
  asm volatile(
      "mma.sync.aligned.m16n8k8.row.col.f32.tf32.tf32.f32 "
      "{%0,%1,%2,%3}, {%4,%5,%6,%7}, {%8,%9}, {%0,%1,%2,%3};\n"
      : "+f"(c[0]), "+f"(c[1]), "+f"(c[2]), "+f"(c[3])
      : "r"(a[0]), "r"(a[1]), "r"(a[2]), "r"(a[3]), "r"(b[0]), "r"(b[1]));
}

// ---------------------------------------------------------------------------
// tf32 pre-rounding pass (float4 vectorized)
// ---------------------------------------------------------------------------
__global__ __launch_bounds__(256) void round_tf32_kernel(const float* __restrict__ in,
                                                         float* __restrict__ out,
                                                         int n4) {
  int i = blockIdx.x * 256 + threadIdx.x;
  if (i >= n4) return;
  float4 v = ((const float4*)in)[i];
  v.x = __uint_as_float(f2tf32(v.x));
  v.y = __uint_as_float(f2tf32(v.y));
  v.z = __uint_as_float(f2tf32(v.z));
  v.w = __uint_as_float(f2tf32(v.w));
  ((float4*)out)[i] = v;
}

// ---------------------------------------------------------------------------
// TF32 tensor-core GEMM on PRE-ROUNDED operands: C = A @ W^T (+ bias)
// 128x128x32 CTA tile, 8 warps, warp tile 64x32, mma m16n8k8.
// No in-loop converts: operands are already tf32-in-f32, feed raw bits.
// ---------------------------------------------------------------------------
template <int BIAS>
__global__ __launch_bounds__(256, 2) void gemm_tf32(const float* __restrict__ A,
                                                    const float* __restrict__ W,
                                                    const float* __restrict__ bias,
                                                    float* __restrict__ C,
                                                    int M, int N, int K) {
  extern __shared__ float sm[];
  const int bm = blockIdx.y * BM;
  const int bn = blockIdx.x * BN;
  const int tid = threadIdx.x;
  const int warp = tid >> 5;
  const int lane = tid & 31;
  const int g = lane >> 2;
  const int t = lane & 3;
  const int wm = (warp >> 2) * 64;
  const int wn = (warp & 3) * 32;

  const float* Ag = A + (size_t)bm * K;
  const float* Wg = W + (size_t)bn * K;
  const int KT = K / BKK;

  float acc[4][4][4];
#pragma unroll
  for (int mi = 0; mi < 4; mi++)
#pragma unroll
    for (int ni = 0; ni < 4; ni++)
#pragma unroll
      for (int c = 0; c < 4; c++) acc[mi][ni][c] = 0.0f;

  auto issue = [&](int kb) {
    float* As = sm + (kb & 1) * STAGE_FLOATS;
    float* Ws = As + BM * LDK;
    int k0 = kb * BKK;
#pragma unroll
    for (int i = 0; i < 4; i++) {
      int lin = tid + i * 256;
      int row = lin >> 3;
      int c4 = lin & 7;
      cp_async16(cvta_smem(As + row * LDK + c4 * 4), Ag + (size_t)row * K + k0 + c4 * 4);
      cp_async16(cvta_smem(Ws + row * LDK + c4 * 4), Wg + (size_t)row * K + k0 + c4 * 4);
    }
    asm volatile("cp.async.commit_group;\n" ::);
  };

  issue(0);

  for (int kb = 0; kb < KT; kb++) {
    if (kb + 1 < KT) {
      issue(kb + 1);
      asm volatile("cp.async.wait_group 1;\n" ::);
    } else {
      asm volatile("cp.async.wait_group 0;\n" ::);
    }
    __syncthreads();

    const float* As = sm + (kb & 1) * STAGE_FLOATS;
    const float* Ws = As + BM * LDK;

#pragma unroll
    for (int ks = 0; ks < 4; ks++) {
      const int k0 = ks * 8;
      uint32_t af[4][4];
      uint32_t bf[4][2];
#pragma unroll
      for (int mi = 0; mi < 4; mi++) {
        const float* p0 = As + (wm + mi * 16 + g) * LDK + k0 + t;
        const float* p1 = p0 + 8 * LDK;
        af[mi][0] = __float_as_uint(p0[0]);
        af[mi][1] = __float_as_uint(p1[0]);
        af[mi][2] = __float_as_uint(p0[4]);
        af[mi][3] = __float_as_uint(p1[4]);
      }
#pragma unroll
      for (int ni = 0; ni < 4; ni++) {
        const float* p = Ws + (wn + ni * 8 + g) * LDK + k0 + t;
        bf[ni][0] = __float_as_uint(p[0]);
        bf[ni][1] = __float_as_uint(p[4]);
      }
#pragma unroll
      for (int mi = 0; mi < 4; mi++)
#pragma unroll
        for (int ni = 0; ni < 4; ni++) mma_tf32(acc[mi][ni], af[mi], bf[ni]);
    }
    __syncthreads();
  }

#pragma unroll
  for (int mi = 0; mi < 4; mi++) {
    int row0 = bm + wm + mi * 16 + g;
#pragma unroll
    for (int ni = 0; ni < 4; ni++) {
      int col = bn + wn + ni * 8 + t * 2;
      float b0 = 0.f, b1 = 0.f;
      if (BIAS) { b0 = bias[col]; b1 = bias[col + 1]; }
      float2 v0 = make_float2(acc[mi][ni][0] + b0, acc[mi][ni][1] + b1);
      float2 v1 = make_float2(acc[mi][ni][2] + b0, acc[mi][ni][3] + b1);
      *(float2*)(C + (size_t)row0 * N + col) = v0;
      *(float2*)(C + (size_t)(row0 + 8) * N + col) = v1;
    }
  }
}

// ---------------------------------------------------------------------------
// RoPE for Q + scatter to [B, NH, S, HD]
// ---------------------------------------------------------------------------
__global__ __launch_bounds__(256) void rope_q_kernel(
    const float* __restrict__ cosb, const float* __restrict__ sinb) {
  int idx = blockIdx.x * 256 + threadIdx.x;
  int d = idx & 127;
  int h = (idx >> 7) & 31;
  int s = (idx >> 12) & 2047;
  int b = idx >> 23;
  float v = g_qproj[idx];
  float p = (d < 64) ? -g_qproj[idx + 64] : g_qproj[idx - 64];
  float out = v * cosb[s * HD + d] + p * sinb[s * HD + d];
  g_q[((size_t)(b * NH + h) * SS + s) * HD + d] = out;
}

// ---------------------------------------------------------------------------
// RoPE for K + scatter K/V as tf32 hi/lo pairs to [B, NKV, S, HD]
// ---------------------------------------------------------------------------
__global__ __launch_bounds__(256) void rope_kv_kernel(
    const float* __restrict__ cosb, const float* __restrict__ sinb) {
  int idx = blockIdx.x * 256 + threadIdx.x;
  int d = idx & 127;
  int n = (idx >> 7) & 7;
  int s = (idx >> 10) & 2047;
  int b = idx >> 21;
  size_t base = ((size_t)(b * SS + s) * (2 * NKV * HD)) + n * (2 * HD);
  float kv = g_kvproj[base + d];
  float kp = (d < 64) ? -g_kvproj[base + d + 64] : g_kvproj[base + d - 64];
  float kout = kv * cosb[s * HD + d] + kp * sinb[s * HD + d];
  float vout = g_kvproj[base + HD + d];
  size_t o = ((size_t)(b * NKV + n) * SS + s) * HD + d;
  float kh = __uint_as_float(f2tf32(kout));
  float vh = __uint_as_float(f2tf32(vout));
  g_khi[o] = kh;
  g_klo[o] = kout - kh;
  g_vhi[o] = vh;
  g_vlo[o] = vout - vh;
}

// ---------------------------------------------------------------------------
// Tensor-core causal flash attention, 3xTF32 compensated. (unchanged except
// epilogue now stores tf32-rounded output so the Wd GEMM needs no converts)
// ---------------------------------------------------------------------------
__global__ __launch_bounds__(256, 1) void attn_mma_kernel() {
  extern __shared__ float sm[];
  const int b = blockIdx.z;
  const int h = blockIdx.y;
  const int qb = (int)gridDim.x - 1 - (int)blockIdx.x;
  const int q0 = qb * 128;
  const int kvh = h >> 2;
  const int tid = threadIdx.x;
  const int warp = tid >> 5;
  const int lane = tid & 31;
  const int g = lane >> 2;
  const int t = lane & 3;
  const int wm = warp * 16;

  float* Qs = sm;
  float* Pw = sm + PS_OFF + warp * (16 * ATT_LDP);

  const float* Qg = g_q + ((size_t)(b * NH + h) * SS + q0) * HD;
  const size_t kvbase = (size_t)(b * NKV + kvh) * SS * HD;
  const float* Khg = g_khi + kvbase;
  const float* Klg = g_klo + kvbase;
  const float* Vhg = g_vhi + kvbase;
  const float* Vlg = g_vlo + kvbase;

  const int nkb = 4 * qb + 4;

  auto cta_copy_tile = [&](float* dst, const float* src, int ld) {
#pragma unroll
    for (int i = 0; i < 4; i++) {
      int lin = tid + i * 256;
      int row = lin >> 5, c4 = lin & 31;
      cp_async16(cvta_smem(dst + row * ld + c4 * 4), src + row * HD + c4 * 4);
    }
  };
  auto loadKV = [&](int kb) {
    int buf = kb & 1;
    size_t off = (size_t)kb * 32 * HD;
    cta_copy_tile(sm + KH_OFF + buf * KCHUNK, Khg + off, ATT_LDK);
    cta_copy_tile(sm + KH_OFF + 2 * KCHUNK + buf * KCHUNK, Klg + off, ATT_LDK);
    cta_copy_tile(sm + VH_OFF + buf * VCHUNK, Vhg + off, ATT_LDV);
    cta_copy_tile(sm + VH_OFF + 2 * VCHUNK + buf * VCHUNK, Vlg + off, ATT_LDV);
  };

#pragma unroll
  for (int i = 0; i < 16; i++) {
    int lin = tid + i * 256;
    int row = lin >> 5, c4 = lin & 31;
    cp_async16(cvta_smem(Qs + row * ATT_LDQ + c4 * 4), Qg + row * HD + c4 * 4);
  }
  loadKV(0);
  asm volatile("cp.async.commit_group;\n" ::);

  float oacc[16][4];
#pragma unroll
  for (int i = 0; i < 16; i++)
#pragma unroll
    for (int c = 0; c < 4; c++) oacc[i][c] = 0.0f;
  float mrow0 = -1e30f, mrow1 = -1e30f, lrow0 = 0.0f, lrow1 = 0.0f;
  const float scale = 0.08838834764831845f;

  for (int kb = 0; kb < nkb; kb++) {
    __syncthreads();
    if (kb + 1 < nkb) loadKV(kb + 1);
    asm volatile("cp.async.commit_group;\n" ::);
    asm volatile("cp.async.wait_group 1;\n" ::);
    __syncthreads();

    const float* Kh = sm + KH_OFF + (kb & 1) * KCHUNK;
    const float* Kl = Kh + 2 * KCHUNK;
    const float* Vh = sm + VH_OFF + (kb & 1) * VCHUNK;
    const float* Vl = Vh + 2 * VCHUNK;

    float sacc[2][4][4];
#pragma unroll
    for (int u = 0; u < 2; u++)
#pragma unroll
      for (int nf = 0; nf < 4; nf++)
#pragma unroll
        for (int c = 0; c < 4; c++) sacc[u][nf][c] = 0.0f;

#pragma unroll
    for (int kp = 0; kp < 8; kp++) {
      uint32_t ah[2][4], al[2][4], bh[2][4][2], bl[2][4][2];
#pragma unroll
      for (int u = 0; u < 2; u++) {
        const int k0 = (kp * 2 + u) * 8;
        const float* qp = Qs + (wm + g) * ATT_LDQ + k0 + t;
        float q0f = qp[0];
        float q1f = qp[8 * ATT_LDQ];
        float q2f = qp[4];
        float q3f = qp[8 * ATT_LDQ + 4];
        ah[u][0] = f2tf32(q0f); al[u][0] = __float_as_uint(q0f - __uint_as_float(ah[u][0]));
        ah[u][1] = f2tf32(q1f); al[u][1] = __float_as_uint(q1f - __uint_as_float(ah[u][1]));
        ah[u][2] = f2tf32(q2f); al[u][2] = __float_as_uint(q2f - __uint_as_float(ah[u][2]));
        ah[u][3] = f2tf32(q3f); al[u][3] = __float_as_uint(q3f - __uint_as_float(ah[u][3]));
#pragma unroll
        for (int nf = 0; nf < 4; nf++) {
          const float* kh0 = Kh + (nf * 8 + g) * ATT_LDK + k0 + t;
          const float* kl0 = Kl + (nf * 8 + g) * ATT_LDK + k0 + t;
          bh[u][nf][0] = __float_as_uint(kh0[0]);
          bh[u][nf][1] = __float_as_uint(kh0[4]);
          bl[u][nf][0] = __float_as_uint(kl0[0]);
          bl[u][nf][1] = __float_as_uint(kl0[4]);
        }
      }
#pragma unroll
      for (int u = 0; u < 2; u++)
#pragma unroll
        for (int nf = 0; nf < 4; nf++) mma_tf32(sacc[u][nf], ah[u], bh[u][nf]);
#pragma unroll
      for (int u = 0; u < 2; u++)
#pragma unroll
        for (int nf = 0; nf < 4; nf++) mma_tf32(sacc[u][nf], al[u], bh[u][nf]);
#pragma unroll
      for (int u = 0; u < 2; u++)
#pragma unroll
        for (int nf = 0; nf < 4; nf++) mma_tf32(sacc[u][nf], ah[u], bl[u][nf]);
    }

    float s[4][4];
#pragma unroll
    for (int nf = 0; nf < 4; nf++)
#pragma unroll
      for (int c = 0; c < 4; c++) s[nf][c] = (sacc[0][nf][c] + sacc[1][nf][c]) * scale;

    if (kb * 32 + 31 > q0 + wm) {
      const int r0i = q0 + wm + g;
      const int r1i = r0i + 8;
#pragma unroll
      for (int nf = 0; nf < 4; nf++) {
        int colb = kb * 32 + nf * 8 + 2 * t;
        if (colb > r0i) s[nf][0] = -1e9f;
        if (colb + 1 > r0i) s[nf][1] = -1e9f;
        if (colb > r1i) s[nf][2] = -1e9f;
        if (colb + 1 > r1i) s[nf][3] = -1e9f;
      }
    }

    float m0 = -1e30f, m1 = -1e30f;
#pragma unroll
    for (int nf = 0; nf < 4; nf++) {
      m0 = fmaxf(m0, fmaxf(s[nf][0], s[nf][1]));
      m1 = fmaxf(m1, fmaxf(s[nf][2], s[nf][3]));
    }
    m0 = fmaxf(m0, __shfl_xor_sync(0xffffffffu, m0, 1));
    m0 = fmaxf(m0, __shfl_xor_sync(0xffffffffu, m0, 2));
    m1 = fmaxf(m1, __shfl_xor_sync(0xffffffffu, m1, 1));
    m1 = fmaxf(m1, __shfl_xor_sync(0xffffffffu, m1, 2));

    float nm0 = fmaxf(mrow0, m0), nm1 = fmaxf(mrow1, m1);
    float c0 = __expf(mrow0 - nm0), c1 = __expf(mrow1 - nm1);
    float r0 = 0.0f, r1 = 0.0f;
#pragma unroll
    for (int nf = 0; nf < 4; nf++) {
      float p00 = __expf(s[nf][0] - nm0);
      float p01 = __expf(s[nf][1] - nm0);
      float p10 = __expf(s[nf][2] - nm1);
      float p11 = __expf(s[nf][3] - nm1);
      r0 += p00 + p01;
      r1 += p10 + p11;
      *(float2*)(Pw + g * ATT_LDP + nf * 8 + 2 * t) = make_float2(p00, p01);
      *(float2*)(Pw + (g + 8) * ATT_LDP + nf * 8 + 2 * t) = make_float2(p10, p11);
    }
    r0 += __shfl_xor_sync(0xffffffffu, r0, 1);
    r0 += __shfl_xor_sync(0xffffffffu, r0, 2);
    r1 += __shfl_xor_sync(0xffffffffu, r1, 1);
    r1 += __shfl_xor_sync(0xffffffffu, r1, 2);
    lrow0 = lrow0 * c0 + r0;
    lrow1 = lrow1 * c1 + r1;
    mrow0 = nm0;
    mrow1 = nm1;
#pragma unroll
    for (int i = 0; i < 16; i++) {
      oacc[i][0] *= c0;
      oacc[i][1] *= c0;
      oacc[i][2] *= c1;
      oacc[i][3] *= c1;
    }
    __syncwarp();

#pragma unroll
    for (int ks = 0; ks < 4; ks++) {
      const int k0 = ks * 8;
      const float* pp = Pw + g * ATT_LDP + k0 + t;
      float p0f = pp[0];
      float p1f = pp[8 * ATT_LDP];
      float p2f = pp[4];
      float p3f = pp[8 * ATT_LDP + 4];
      uint32_t pah[4], pal[4];
      pah[0] = f2tf32(p0f); pal[0] = __float_as_uint(p0f - __uint_as_float(pah[0]));
      pah[1] = f2tf32(p1f); pal[1] = __float_as_uint(p1f - __uint_as_float(pah[1]));
      pah[2] = f2tf32(p2f); pal[2] = __float_as_uint(p2f - __uint_as_float(pah[2]));
      pah[3] = f2tf32(p3f); pal[3] = __float_as_uint(p3f - __uint_as_float(pah[3]));
#pragma unroll
      for (int nh = 0; nh < 2; nh++) {
        uint32_t vbh[8][2], vbl[8][2];
#pragma unroll
        for (int j = 0; j < 8; j++) {
          int n0 = (nh * 8 + j) * 8 + g;
          const float* vp = Vh + (k0 + t) * ATT_LDV + n0;
          const float* vl = Vl + (k0 + t) * ATT_LDV + n0;
          vbh[j][0] = __float_as_uint(vp[0]);
          vbh[j][1] = __float_as_uint(vp[4 * ATT_LDV]);
          vbl[j][0] = __float_as_uint(vl[0]);
          vbl[j][1] = __float_as_uint(vl[4 * ATT_LDV]);
        }
#pragma unroll
        for (int j = 0; j < 8; j++) mma_tf32(oacc[nh * 8 + j], pah, vbh[j]);
#pragma unroll
        for (int j = 0; j < 8; j++) mma_tf32(oacc[nh * 8 + j], pal, vbh[j]);
#pragma unroll
        for (int j = 0; j < 8; j++) mma_tf32(oacc[nh * 8 + j], pah, vbl[j]);
      }
    }
  }

  // ---- epilogue: store tf32-ROUNDED output (free pre-round for Wd GEMM) ----
  float inv0 = 1.0f / lrow0;
  float inv1 = 1.0f / lrow1;
  const int row0 = q0 + wm + g;
  float* o0 = g_attn + ((size_t)(b * SS) + row0) * HIDD + h * HD;
  float* o1 = o0 + (size_t)8 * HIDD;
#pragma unroll
  for (int nf = 0; nf < 16; nf++) {
    float2 a = make_float2(__uint_as_float(f2tf32(oacc[nf][0] * inv0)),
                           __uint_as_float(f2tf32(oacc[nf][1] * inv0)));
    float2 c = make_float2(__uint_as_float(f2tf32(oacc[nf][2] * inv1)),
                           __uint_as_float(f2tf32(oacc[nf][3] * inv1)));
    *(float2*)(o0 + nf * 8 + 2 * t) = a;
    *(float2*)(o1 + nf * 8 + 2 * t) = c;
  }
}

// ---------------------------------------------------------------------------
extern "C" void kernel_launch(void* const* d_in, const int* in_sizes, int n_in,
                              void* d_out, int out_size) {
  const float* hidden = (const float*)d_in[0];
  const float* cosb = (const float*)d_in[2];
  const float* sinb = (const float*)d_in[3];
  const float* Wq = (const float*)d_in[4];
  const float* Wkv = (const float*)d_in[5];
  const float* Wd = (const float*)d_in[6];
  const float* bd = (const float*)d_in[7];
  float* out = (float*)d_out;

  float *qproj, *kvproj, *attn, *hidr, *wqr, *wkvr, *wdr;
  cudaGetSymbolAddress((void**)&qproj, g_qproj);
  cudaGetSymbolAddress((void**)&kvproj, g_kvproj);
  cudaGetSymbolAddress((void**)&attn, g_attn);
  cudaGetSymbolAddress((void**)&hidr, g_hidr);
  cudaGetSymbolAddress((void**)&wqr, g_wqr);
  cudaGetSymbolAddress((void**)&wkvr, g_wkvr);
  cudaGetSymbolAddress((void**)&wdr, g_wdr);

  const int M = BB * SS;
  const int gemm_smem = 2 * STAGE_FLOATS * 4;

  cudaFuncSetAttribute(gemm_tf32<0>, cudaFuncAttributeMaxDynamicSharedMemorySize, gemm_smem);
  cudaFuncSetAttribute(gemm_tf32<1>, cudaFuncAttributeMaxDynamicSharedMemorySize, gemm_smem);
  cudaFuncSetAttribute(attn_mma_kernel, cudaFuncAttributeMaxDynamicSharedMemorySize, ATT_SMEM);

  // 0) tf32 pre-rounding of GEMM operands
  {
    int n4h = (BB * SS * HIDD) / 4;
    round_tf32_kernel<<<(n4h + 255) / 256, 256>>>(hidden, hidr, n4h);
    int n4q = (HIDD * HIDD) / 4;
    round_tf32_kernel<<<(n4q + 255) / 256, 256>>>(Wq, wqr, n4q);
    int n4kv = (2 * NKV * HD * HIDD) / 4;
    round_tf32_kernel<<<(n4kv + 255) / 256, 256>>>(Wkv, wkvr, n4kv);
    round_tf32_kernel<<<(n4q + 255) / 256, 256>>>(Wd, wdr, n4q);
  }

  // 1) Q projection
  {
    dim3 grid(HIDD / BN, M / BM);
    gemm_tf32<0><<<grid, 256, gemm_smem>>>(hidr, wqr, nullptr, qproj, M, HIDD, HIDD);
  }
  // 2) KV projection
  {
    dim3 grid((2 * NKV * HD) / BN, M / BM);
    gemm_tf32<0><<<grid, 256, gemm_smem>>>(hidr, wkvr, nullptr, kvproj, M, 2 * NKV * HD, HIDD);
  }
  // 3) RoPE + scatter
  rope_q_kernel<<<(BB * SS * HIDD) / 256, 256>>>(cosb, sinb);
  rope_kv_kernel<<<(BB * SS * NKV * HD) / 256, 256>>>(cosb, sinb);

  // 4) tensor-core flash attention (epilogue pre-rounds its output)
  {
    dim3 grid(SS / 128, NH, BB);
    attn_mma_kernel<<<grid, 256, ATT_SMEM>>>();
  }

  // 5) output projection with bias
  {
    dim3 grid(HIDD / BN, M / BM);
    gemm_tf32<1><<<grid, 256, gemm_smem>>>(attn, wdr, bd, out, M, HIDD, HIDD);
  }
}

// round 9
// speedup vs baseline: 1.5322x; 1.5322x over previous
#include <cuda_runtime.h>
#include <cstdint>

// Problem constants
#define BB   2
#define SS   2048
#define HIDD 4096
#define NH   32
#define NKV  8
#define HD   128

// GEMM tiling
#define BM 128
#define BN 128
#define BKK 32
#define LDK 36
#define STAGE_FLOATS ((BM + BN) * LDK)

// Attention tiling / smem layout (floats)
#define ATT_LDQ 132
#define ATT_LDK 132
#define ATT_LDV 136
#define ATT_LDP 36
#define KH_OFF (128 * ATT_LDQ)
#define KCHUNK (32 * ATT_LDK)
#define VH_OFF (KH_OFF + 4 * KCHUNK)
#define VCHUNK (32 * ATT_LDV)
#define PS_OFF (VH_OFF + 4 * VCHUNK)
#define ATT_SMEM ((PS_OFF + 8 * 16 * ATT_LDP) * 4)  // 223232 bytes

// ---------------- scratch (static device globals; no runtime alloc) --------
__device__ float g_qproj[(size_t)BB * SS * HIDD];
__device__ float g_kvproj[(size_t)BB * SS * 2 * NKV * HD];
__device__ float g_q[(size_t)BB * NH * SS * HD];
__device__ float g_khi[(size_t)BB * NKV * SS * HD];
__device__ float g_klo[(size_t)BB * NKV * SS * HD];
__device__ float g_vhi[(size_t)BB * NKV * SS * HD];
__device__ float g_vlo[(size_t)BB * NKV * SS * HD];
__device__ float g_attn[(size_t)BB * SS * HIDD];

// ---------------------------------------------------------------------------
// helpers
// ---------------------------------------------------------------------------
__device__ __forceinline__ uint32_t cvta_smem(const void* p) {
  return (uint32_t)__cvta_generic_to_shared(p);
}

__device__ __forceinline__ void cp_async16(uint32_t saddr, const void* gptr) {
  asm volatile("cp.async.cg.shared.global [%0], [%1], 16;\n" ::"r"(saddr), "l"(gptr));
}

__device__ __forceinline__ uint32_t f2tf32(float x) {
  uint32_t u;
  asm("cvt.rna.tf32.f32 %0, %1;\n" : "=r"(u) : "f"(x));
  return u;
}

__device__ __forceinline__ void mma_tf32(float* c, const uint32_t* a, const uint32_t* b) {
  asm volatile(
      "mma.sync.aligned.m16n8k8.row.col.f32.tf32.tf32.f32 "
      "{%0,%1,%2,%3}, {%4,%5,%6,%7}, {%8,%9}, {%0,%1,%2,%3};\n"
      : "+f"(c[0]), "+f"(c[1]), "+f"(c[2]), "+f"(c[3])
      : "r"(a[0]), "r"(a[1]), "r"(a[2]), "r"(a[3]), "r"(b[0]), "r"(b[1]));
}

// ---------------------------------------------------------------------------
// TF32 tensor-core GEMM: C[M,N] = A[M,K] @ W[N,K]^T (+ bias[N])
// 128x128x32 CTA tile, 4 warps (2x2), warp tile 64x64, mma m16n8k8.
// 2-stage cp.async pipeline. In-loop cvt.rna (round-7 numerics).
// ---------------------------------------------------------------------------
template <int BIAS>
__global__ __launch_bounds__(128, 2) void gemm_tf32(const float* __restrict__ A,
                                                    const float* __restrict__ W,
                                                    const float* __restrict__ bias,
                                                    float* __restrict__ C,
                                                    int M, int N, int K) {
  extern __shared__ float sm[];
  const int bm = blockIdx.y * BM;
  const int bn = blockIdx.x * BN;
  const int tid = threadIdx.x;
  const int warp = tid >> 5;
  const int lane = tid & 31;
  const int g = lane >> 2;
  const int t = lane & 3;
  const int wm = (warp >> 1) * 64;  // warp row offset (2x2 warp grid)
  const int wn = (warp & 1) * 64;   // warp col offset

  const float* Ag = A + (size_t)bm * K;
  const float* Wg = W + (size_t)bn * K;
  const int KT = K / BKK;

  float acc[4][8][4];
#pragma unroll
  for (int mi = 0; mi < 4; mi++)
#pragma unroll
    for (int ni = 0; ni < 8; ni++)
#pragma unroll
      for (int c = 0; c < 4; c++) acc[mi][ni][c] = 0.0f;

  auto issue = [&](int kb) {
    float* As = sm + (kb & 1) * STAGE_FLOATS;
    float* Ws = As + BM * LDK;
    int k0 = kb * BKK;
#pragma unroll
    for (int i = 0; i < 8; i++) {
      int lin = tid + i * 128;     // 0..1023
      int row = lin >> 3;          // 0..127
      int c4 = lin & 7;            // 0..7
      cp_async16(cvta_smem(As + row * LDK + c4 * 4), Ag + (size_t)row * K + k0 + c4 * 4);
      cp_async16(cvta_smem(Ws + row * LDK + c4 * 4), Wg + (size_t)row * K + k0 + c4 * 4);
    }
    asm volatile("cp.async.commit_group;\n" ::);
  };

  issue(0);

  for (int kb = 0; kb < KT; kb++) {
    if (kb + 1 < KT) {
      issue(kb + 1);
      asm volatile("cp.async.wait_group 1;\n" ::);
    } else {
      asm volatile("cp.async.wait_group 0;\n" ::);
    }
    __syncthreads();

    const float* As = sm + (kb & 1) * STAGE_FLOATS;
    const float* Ws = As + BM * LDK;

#pragma unroll
    for (int ks = 0; ks < 4; ks++) {
      const int k0 = ks * 8;
      uint32_t af[4][4];
      uint32_t bf[8][2];
#pragma unroll
      for (int mi = 0; mi < 4; mi++) {
        const float* p0 = As + (wm + mi * 16 + g) * LDK + k0 + t;
        const float* p1 = p0 + 8 * LDK;
        af[mi][0] = f2tf32(p0[0]);
        af[mi][1] = f2tf32(p1[0]);
        af[mi][2] = f2tf32(p0[4]);
        af[mi][3] = f2tf32(p1[4]);
      }
#pragma unroll
      for (int ni = 0; ni < 8; ni++) {
        const float* p = Ws + (wn + ni * 8 + g) * LDK + k0 + t;
        bf[ni][0] = f2tf32(p[0]);
        bf[ni][1] = f2tf32(p[4]);
      }
#pragma unroll
      for (int mi = 0; mi < 4; mi++)
#pragma unroll
        for (int ni = 0; ni < 8; ni++) mma_tf32(acc[mi][ni], af[mi], bf[ni]);
    }
    __syncthreads();
  }

#pragma unroll
  for (int mi = 0; mi < 4; mi++) {
    int row0 = bm + wm + mi * 16 + g;
#pragma unroll
    for (int ni = 0; ni < 8; ni++) {
      int col = bn + wn + ni * 8 + t * 2;
      float b0 = 0.f, b1 = 0.f;
      if (BIAS) { b0 = bias[col]; b1 = bias[col + 1]; }
      float2 v0 = make_float2(acc[mi][ni][0] + b0, acc[mi][ni][1] + b1);
      float2 v1 = make_float2(acc[mi][ni][2] + b0, acc[mi][ni][3] + b1);
      *(float2*)(C + (size_t)row0 * N + col) = v0;
      *(float2*)(C + (size_t)(row0 + 8) * N + col) = v1;
    }
  }
}

// ---------------------------------------------------------------------------
// RoPE for Q + scatter to [B, NH, S, HD]
// ---------------------------------------------------------------------------
__global__ __launch_bounds__(256) void rope_q_kernel(
    const float* __restrict__ cosb, const float* __restrict__ sinb) {
  int idx = blockIdx.x * 256 + threadIdx.x;
  int d = idx & 127;
  int h = (idx >> 7) & 31;
  int s = (idx >> 12) & 2047;
  int b = idx >> 23;
  float v = g_qproj[idx];
  float p = (d < 64) ? -g_qproj[idx + 64] : g_qproj[idx - 64];
  float out = v * cosb[s * HD + d] + p * sinb[s * HD + d];
  g_q[((size_t)(b * NH + h) * SS + s) * HD + d] = out;
}

// ---------------------------------------------------------------------------
// RoPE for K + scatter K/V as tf32 hi/lo pairs to [B, NKV, S, HD]
// ---------------------------------------------------------------------------
__global__ __launch_bounds__(256) void rope_kv_kernel(
    const float* __restrict__ cosb, const float* __restrict__ sinb) {
  int idx = blockIdx.x * 256 + threadIdx.x;
  int d = idx & 127;
  int n = (idx >> 7) & 7;
  int s = (idx >> 10) & 2047;
  int b = idx >> 21;
  size_t base = ((size_t)(b * SS + s) * (2 * NKV * HD)) + n * (2 * HD);
  float kv = g_kvproj[base + d];
  float kp = (d < 64) ? -g_kvproj[base + d + 64] : g_kvproj[base + d - 64];
  float kout = kv * cosb[s * HD + d] + kp * sinb[s * HD + d];
  float vout = g_kvproj[base + HD + d];
  size_t o = ((size_t)(b * NKV + n) * SS + s) * HD + d;
  float kh = __uint_as_float(f2tf32(kout));
  float vh = __uint_as_float(f2tf32(vout));
  g_khi[o] = kh;
  g_klo[o] = kout - kh;
  g_vhi[o] = vh;
  g_vlo[o] = vout - vh;
}

// ---------------------------------------------------------------------------
// Tensor-core causal flash attention, 3xTF32 compensated (round-7 version).
// ---------------------------------------------------------------------------
__global__ __launch_bounds__(256, 1) void attn_mma_kernel() {
  extern __shared__ float sm[];
  const int b = blockIdx.z;
  const int h = blockIdx.y;
  const int qb = (int)gridDim.x - 1 - (int)blockIdx.x;
  const int q0 = qb * 128;
  const int kvh = h >> 2;
  const int tid = threadIdx.x;
  const int warp = tid >> 5;
  const int lane = tid & 31;
  const int g = lane >> 2;
  const int t = lane & 3;
  const int wm = warp * 16;

  float* Qs = sm;
  float* Pw = sm + PS_OFF + warp * (16 * ATT_LDP);

  const float* Qg = g_q + ((size_t)(b * NH + h) * SS + q0) * HD;
  const size_t kvbase = (size_t)(b * NKV + kvh) * SS * HD;
  const float* Khg = g_khi + kvbase;
  const float* Klg = g_klo + kvbase;
  const float* Vhg = g_vhi + kvbase;
  const float* Vlg = g_vlo + kvbase;

  const int nkb = 4 * qb + 4;

  auto cta_copy_tile = [&](float* dst, const float* src, int ld) {
#pragma unroll
    for (int i = 0; i < 4; i++) {
      int lin = tid + i * 256;
      int row = lin >> 5, c4 = lin & 31;
      cp_async16(cvta_smem(dst + row * ld + c4 * 4), src + row * HD + c4 * 4);
    }
  };
  auto loadKV = [&](int kb) {
    int buf = kb & 1;
    size_t off = (size_t)kb * 32 * HD;
    cta_copy_tile(sm + KH_OFF + buf * KCHUNK, Khg + off, ATT_LDK);
    cta_copy_tile(sm + KH_OFF + 2 * KCHUNK + buf * KCHUNK, Klg + off, ATT_LDK);
    cta_copy_tile(sm + VH_OFF + buf * VCHUNK, Vhg + off, ATT_LDV);
    cta_copy_tile(sm + VH_OFF + 2 * VCHUNK + buf * VCHUNK, Vlg + off, ATT_LDV);
  };

#pragma unroll
  for (int i = 0; i < 16; i++) {
    int lin = tid + i * 256;
    int row = lin >> 5, c4 = lin & 31;
    cp_async16(cvta_smem(Qs + row * ATT_LDQ + c4 * 4), Qg + row * HD + c4 * 4);
  }
  loadKV(0);
  asm volatile("cp.async.commit_group;\n" ::);

  float oacc[16][4];
#pragma unroll
  for (int i = 0; i < 16; i++)
#pragma unroll
    for (int c = 0; c < 4; c++) oacc[i][c] = 0.0f;
  float mrow0 = -1e30f, mrow1 = -1e30f, lrow0 = 0.0f, lrow1 = 0.0f;
  const float scale = 0.08838834764831845f;

  for (int kb = 0; kb < nkb; kb++) {
    __syncthreads();
    if (kb + 1 < nkb) loadKV(kb + 1);
    asm volatile("cp.async.commit_group;\n" ::);
    asm volatile("cp.async.wait_group 1;\n" ::);
    __syncthreads();

    const float* Kh = sm + KH_OFF + (kb & 1) * KCHUNK;
    const float* Kl = Kh + 2 * KCHUNK;
    const float* Vh = sm + VH_OFF + (kb & 1) * VCHUNK;
    const float* Vl = Vh + 2 * VCHUNK;

    float sacc[2][4][4];
#pragma unroll
    for (int u = 0; u < 2; u++)
#pragma unroll
      for (int nf = 0; nf < 4; nf++)
#pragma unroll
        for (int c = 0; c < 4; c++) sacc[u][nf][c] = 0.0f;

#pragma unroll
    for (int kp = 0; kp < 8; kp++) {
      uint32_t ah[2][4], al[2][4], bh[2][4][2], bl[2][4][2];
#pragma unroll
      for (int u = 0; u < 2; u++) {
        const int k0 = (kp * 2 + u) * 8;
        const float* qp = Qs + (wm + g) * ATT_LDQ + k0 + t;
        float q0f = qp[0];
        float q1f = qp[8 * ATT_LDQ];
        float q2f = qp[4];
        float q3f = qp[8 * ATT_LDQ + 4];
        ah[u][0] = f2tf32(q0f); al[u][0] = __float_as_uint(q0f - __uint_as_float(ah[u][0]));
        ah[u][1] = f2tf32(q1f); al[u][1] = __float_as_uint(q1f - __uint_as_float(ah[u][1]));
        ah[u][2] = f2tf32(q2f); al[u][2] = __float_as_uint(q2f - __uint_as_float(ah[u][2]));
        ah[u][3] = f2tf32(q3f); al[u][3] = __float_as_uint(q3f - __uint_as_float(ah[u][3]));
#pragma unroll
        for (int nf = 0; nf < 4; nf++) {
          const float* kh0 = Kh + (nf * 8 + g) * ATT_LDK + k0 + t;
          const float* kl0 = Kl + (nf * 8 + g) * ATT_LDK + k0 + t;
          bh[u][nf][0] = __float_as_uint(kh0[0]);
          bh[u][nf][1] = __float_as_uint(kh0[4]);
          bl[u][nf][0] = __float_as_uint(kl0[0]);
          bl[u][nf][1] = __float_as_uint(kl0[4]);
        }
      }
#pragma unroll
      for (int u = 0; u < 2; u++)
#pragma unroll
        for (int nf = 0; nf < 4; nf++) mma_tf32(sacc[u][nf], ah[u], bh[u][nf]);
#pragma unroll
      for (int u = 0; u < 2; u++)
#pragma unroll
        for (int nf = 0; nf < 4; nf++) mma_tf32(sacc[u][nf], al[u], bh[u][nf]);
#pragma unroll
      for (int u = 0; u < 2; u++)
#pragma unroll
        for (int nf = 0; nf < 4; nf++) mma_tf32(sacc[u][nf], ah[u], bl[u][nf]);
    }

    float s[4][4];
#pragma unroll
    for (int nf = 0; nf < 4; nf++)
#pragma unroll
      for (int c = 0; c < 4; c++) s[nf][c] = (sacc[0][nf][c] + sacc[1][nf][c]) * scale;

    if (kb * 32 + 31 > q0 + wm) {
      const int r0i = q0 + wm + g;
      const int r1i = r0i + 8;
#pragma unroll
      for (int nf = 0; nf < 4; nf++) {
        int colb = kb * 32 + nf * 8 + 2 * t;
        if (colb > r0i) s[nf][0] = -1e9f;
        if (colb + 1 > r0i) s[nf][1] = -1e9f;
        if (colb > r1i) s[nf][2] = -1e9f;
        if (colb + 1 > r1i) s[nf][3] = -1e9f;
      }
    }

    float m0 = -1e30f, m1 = -1e30f;
#pragma unroll
    for (int nf = 0; nf < 4; nf++) {
      m0 = fmaxf(m0, fmaxf(s[nf][0], s[nf][1]));
      m1 = fmaxf(m1, fmaxf(s[nf][2], s[nf][3]));
    }
    m0 = fmaxf(m0, __shfl_xor_sync(0xffffffffu, m0, 1));
    m0 = fmaxf(m0, __shfl_xor_sync(0xffffffffu, m0, 2));
    m1 = fmaxf(m1, __shfl_xor_sync(0xffffffffu, m1, 1));
    m1 = fmaxf(m1, __shfl_xor_sync(0xffffffffu, m1, 2));

    float nm0 = fmaxf(mrow0, m0), nm1 = fmaxf(mrow1, m1);
    float c0 = __expf(mrow0 - nm0), c1 = __expf(mrow1 - nm1);
    float r0 = 0.0f, r1 = 0.0f;
#pragma unroll
    for (int nf = 0; nf < 4; nf++) {
      float p00 = __expf(s[nf][0] - nm0);
      float p01 = __expf(s[nf][1] - nm0);
      float p10 = __expf(s[nf][2] - nm1);
      float p11 = __expf(s[nf][3] - nm1);
      r0 += p00 + p01;
      r1 += p10 + p11;
      *(float2*)(Pw + g * ATT_LDP + nf * 8 + 2 * t) = make_float2(p00, p01);
      *(float2*)(Pw + (g + 8) * ATT_LDP + nf * 8 + 2 * t) = make_float2(p10, p11);
    }
    r0 += __shfl_xor_sync(0xffffffffu, r0, 1);
    r0 += __shfl_xor_sync(0xffffffffu, r0, 2);
    r1 += __shfl_xor_sync(0xffffffffu, r1, 1);
    r1 += __shfl_xor_sync(0xffffffffu, r1, 2);
    lrow0 = lrow0 * c0 + r0;
    lrow1 = lrow1 * c1 + r1;
    mrow0 = nm0;
    mrow1 = nm1;
#pragma unroll
    for (int i = 0; i < 16; i++) {
      oacc[i][0] *= c0;
      oacc[i][1] *= c0;
      oacc[i][2] *= c1;
      oacc[i][3] *= c1;
    }
    __syncwarp();

#pragma unroll
    for (int ks = 0; ks < 4; ks++) {
      const int k0 = ks * 8;
      const float* pp = Pw + g * ATT_LDP + k0 + t;
      float p0f = pp[0];
      float p1f = pp[8 * ATT_LDP];
      float p2f = pp[4];
      float p3f = pp[8 * ATT_LDP + 4];
      uint32_t pah[4], pal[4];
      pah[0] = f2tf32(p0f); pal[0] = __float_as_uint(p0f - __uint_as_float(pah[0]));
      pah[1] = f2tf32(p1f); pal[1] = __float_as_uint(p1f - __uint_as_float(pah[1]));
      pah[2] = f2tf32(p2f); pal[2] = __float_as_uint(p2f - __uint_as_float(pah[2]));
      pah[3] = f2tf32(p3f); pal[3] = __float_as_uint(p3f - __uint_as_float(pah[3]));
#pragma unroll
      for (int nh = 0; nh < 2; nh++) {
        uint32_t vbh[8][2], vbl[8][2];
#pragma unroll
        for (int j = 0; j < 8; j++) {
          int n0 = (nh * 8 + j) * 8 + g;
          const float* vp = Vh + (k0 + t) * ATT_LDV + n0;
          const float* vl = Vl + (k0 + t) * ATT_LDV + n0;
          vbh[j][0] = __float_as_uint(vp[0]);
          vbh[j][1] = __float_as_uint(vp[4 * ATT_LDV]);
          vbl[j][0] = __float_as_uint(vl[0]);
          vbl[j][1] = __float_as_uint(vl[4 * ATT_LDV]);
        }
#pragma unroll
        for (int j = 0; j < 8; j++) mma_tf32(oacc[nh * 8 + j], pah, vbh[j]);
#pragma unroll
        for (int j = 0; j < 8; j++) mma_tf32(oacc[nh * 8 + j], pal, vbh[j]);
#pragma unroll
        for (int j = 0; j < 8; j++) mma_tf32(oacc[nh * 8 + j], pah, vbl[j]);
      }
    }
  }

  float inv0 = 1.0f / lrow0;
  float inv1 = 1.0f / lrow1;
  const int row0 = q0 + wm + g;
  float* o0 = g_attn + ((size_t)(b * SS) + row0) * HIDD + h * HD;
  float* o1 = o0 + (size_t)8 * HIDD;
#pragma unroll
  for (int nf = 0; nf < 16; nf++) {
    *(float2*)(o0 + nf * 8 + 2 * t) = make_float2(oacc[nf][0] * inv0, oacc[nf][1] * inv0);
    *(float2*)(o1 + nf * 8 + 2 * t) = make_float2(oacc[nf][2] * inv1, oacc[nf][3] * inv1);
  }
}

// ---------------------------------------------------------------------------
extern "C" void kernel_launch(void* const* d_in, const int* in_sizes, int n_in,
                              void* d_out, int out_size) {
  const float* hidden = (const float*)d_in[0];
  const float* cosb = (const float*)d_in[2];
  const float* sinb = (const float*)d_in[3];
  const float* Wq = (const float*)d_in[4];
  const float* Wkv = (const float*)d_in[5];
  const float* Wd = (const float*)d_in[6];
  const float* bd = (const float*)d_in[7];
  float* out = (float*)d_out;

  float *qproj, *kvproj, *attn;
  cudaGetSymbolAddress((void**)&qproj, g_qproj);
  cudaGetSymbolAddress((void**)&kvproj, g_kvproj);
  cudaGetSymbolAddress((void**)&attn, g_attn);

  const int M = BB * SS;
  const int gemm_smem = 2 * STAGE_FLOATS * 4;

  cudaFuncSetAttribute(gemm_tf32<0>, cudaFuncAttributeMaxDynamicSharedMemorySize, gemm_smem);
  cudaFuncSetAttribute(gemm_tf32<1>, cudaFuncAttributeMaxDynamicSharedMemorySize, gemm_smem);
  cudaFuncSetAttribute(attn_mma_kernel, cudaFuncAttributeMaxDynamicSharedMemorySize, ATT_SMEM);

  // 1) Q projection
  {
    dim3 grid(HIDD / BN, M / BM);
    gemm_tf32<0><<<grid, 128, gemm_smem>>>(hidden, Wq, nullptr, qproj, M, HIDD, HIDD);
  }
  // 2) KV projection
  {
    dim3 grid((2 * NKV * HD) / BN, M / BM);
    gemm_tf32<0><<<grid, 128, gemm_smem>>>(hidden, Wkv, nullptr, kvproj, M, 2 * NKV * HD, HIDD);
  }
  // 3) RoPE + scatter
  rope_q_kernel<<<(BB * SS * HIDD) / 256, 256>>>(cosb, sinb);
  rope_kv_kernel<<<(BB * SS * NKV * HD) / 256, 256>>>(cosb, sinb);

  // 4) tensor-core flash attention
  {
    dim3 grid(SS / 128, NH, BB);
    attn_mma_kernel<<<grid, 256, ATT_SMEM>>>();
  }

  // 5) output projection with bias
  {
    dim3 grid(HIDD / BN, M / BM);
    gemm_tf32<1><<<grid, 128, gemm_smem>>>(attn, Wd, bd, out, M, HIDD, HIDD);
  }
}